// round 9
// baseline (speedup 1.0000x reference)
#include <cuda_runtime.h>
#include <cuda_fp16.h>

#define BS   2048
#define HD   1024
#define NE   8
#define FF   512
#define TWOF 1024
#define EPSV 1e-9f

// ======================= device scratch =======================
__device__ int    g_valid_cnt[NE];
__device__ int    g_mis_cnt[NE];
__device__ int    g_expert_cnt[NE];
__device__ int    g_expert_tok[NE][BS];     // packed token*2 + k
__device__ float  g_expert_w[NE][BS];
__device__ int    g_sel[BS][2];
__device__ float  g_rw[BS][2];
__device__ __half g_xr[BS][HD];             // fp16 x (4 MB)
__device__ __half g_W1[NE][HD][TWOF];       // gate_up fp16, SAME layout as input (k-major rows)
__device__ __half g_W2[NE][FF][HD];         // down fp16, same layout (k=f rows)
__device__ __half g_act[NE][BS][FF];        // silu(g)*u fp16

// ======================= PTX helpers =======================
__device__ __forceinline__ unsigned smem_u32(const void* p) {
    unsigned a;
    asm("{ .reg .u64 t; cvta.to.shared.u64 t, %1; cvt.u32.u64 %0, t; }" : "=r"(a) : "l"(p));
    return a;
}
#define CP16(s, g) asm volatile("cp.async.cg.shared.global [%0], [%1], 16;" :: "r"(s), "l"(g))
#define CPCOMMIT() asm volatile("cp.async.commit_group;" ::: "memory")
#define CPWAIT(n)  asm volatile("cp.async.wait_group %0;" :: "n"(n) : "memory")
#define LDSM4(r0, r1, r2, r3, a) \
    asm volatile("ldmatrix.sync.aligned.m8n8.x4.shared.b16 {%0,%1,%2,%3}, [%4];" \
        : "=r"(r0), "=r"(r1), "=r"(r2), "=r"(r3) : "r"(a))
#define LDSM4T(r0, r1, r2, r3, a) \
    asm volatile("ldmatrix.sync.aligned.m8n8.x4.trans.shared.b16 {%0,%1,%2,%3}, [%4];" \
        : "=r"(r0), "=r"(r1), "=r"(r2), "=r"(r3) : "r"(a))
#define MMAH(c, a0, a1, a2, a3, b0, b1) \
    asm volatile("mma.sync.aligned.m16n8k16.row.col.f32.f16.f16.f32 " \
        "{%0,%1,%2,%3}, {%4,%5,%6,%7}, {%8,%9}, {%0,%1,%2,%3};" \
        : "+f"((c)[0]), "+f"((c)[1]), "+f"((c)[2]), "+f"((c)[3]) \
        : "r"(a0), "r"(a1), "r"(a2), "r"(a3), "r"(b0), "r"(b1))

// dynamic smem: [0,512) tsp ints, [512,1024) tw floats, 3 stages x (A 16KB + B 16KB)
// A tile: 128 rows x 128B ; B tile: 64 k-rows x 256B
#define SMH_A(s) (1024 + (s) * 32768)
#define SMH_B(s) (1024 + (s) * 32768 + 16384)
#define SMH_BYTES (1024 + 3 * 32768)   // 99328

// ======================= K_prep: fp32->fp16 copies + out zero + counters =======================
#define W1_H8 (NE * HD * TWOF / 8)   // 1048576 half8 units
#define W2_H8 (NE * FF * HD / 8)     // 524288
#define ZO_F4 (BS * HD / 4)          // 524288 float4
__global__ void __launch_bounds__(256) k_prep(
    const float* __restrict__ gup, const float* __restrict__ down, float4* __restrict__ out)
{
    unsigned gi = blockIdx.x * 256u + threadIdx.x;
    if (blockIdx.x == 0 && threadIdx.x < NE) {
        g_valid_cnt[threadIdx.x] = 0; g_mis_cnt[threadIdx.x] = 0; g_expert_cnt[threadIdx.x] = 0;
    }
    if (gi < W1_H8) {
        const float4* s = (const float4*)gup + 2u * gi;
        float4 a = s[0], b = s[1];
        __half2 h0 = __floats2half2_rn(a.x, a.y), h1 = __floats2half2_rn(a.z, a.w);
        __half2 h2 = __floats2half2_rn(b.x, b.y), h3 = __floats2half2_rn(b.z, b.w);
        uint4 v = make_uint4(*(unsigned*)&h0, *(unsigned*)&h1, *(unsigned*)&h2, *(unsigned*)&h3);
        ((uint4*)&g_W1[0][0][0])[gi] = v;
    } else if (gi < W1_H8 + W2_H8) {
        unsigned j = gi - W1_H8;
        const float4* s = (const float4*)down + 2u * j;
        float4 a = s[0], b = s[1];
        __half2 h0 = __floats2half2_rn(a.x, a.y), h1 = __floats2half2_rn(a.z, a.w);
        __half2 h2 = __floats2half2_rn(b.x, b.y), h3 = __floats2half2_rn(b.z, b.w);
        uint4 v = make_uint4(*(unsigned*)&h0, *(unsigned*)&h1, *(unsigned*)&h2, *(unsigned*)&h3);
        ((uint4*)&g_W2[0][0][0])[j] = v;
    } else if (gi < W1_H8 + W2_H8 + ZO_F4) {
        out[gi - W1_H8 - W2_H8] = make_float4(0.f, 0.f, 0.f, 0.f);
    }
}
#define PREP_BLOCKS ((W1_H8 + W2_H8 + ZO_F4 + 255) / 256)

// ======================= K1: router, 2 warps/token + x -> fp16 =======================
__global__ void __launch_bounds__(256) k_router(
    const float* __restrict__ x, const float* __restrict__ gw,
    const int* __restrict__ tmod, const int* __restrict__ emod)
{
    __shared__ float sgw[NE * HD];
    __shared__ float part[8][NE];
    for (int i = threadIdx.x; i < NE * HD / 4; i += blockDim.x)
        *(float4*)&sgw[i * 4] = ((const float4*)gw)[i];
    __syncthreads();

    int warp = threadIdx.x >> 5, lane = threadIdx.x & 31;
    int t = blockIdx.x * 4 + (warp >> 1);    // 512 blocks * 4 tokens
    int hf = warp & 1;

    const float4* xr = (const float4*)(x + (size_t)t * HD) + hf * 128;
    __half2* xo = (__half2*)&g_xr[t][0] + hf * 256;
    float acc[NE];
    #pragma unroll
    for (int e = 0; e < NE; e++) acc[e] = 0.f;
    #pragma unroll
    for (int i = 0; i < 4; i++) {
        int q = lane + i * 32;               // 0..127
        float4 xv = xr[q];
        xo[q * 2 + 0] = __floats2half2_rn(xv.x, xv.y);
        xo[q * 2 + 1] = __floats2half2_rn(xv.z, xv.w);
        #pragma unroll
        for (int e = 0; e < NE; e++) {
            const float4 wv = *(const float4*)&sgw[e * HD + (hf * 128 + q) * 4];
            acc[e] = fmaf(xv.x, wv.x, acc[e]);
            acc[e] = fmaf(xv.y, wv.y, acc[e]);
            acc[e] = fmaf(xv.z, wv.z, acc[e]);
            acc[e] = fmaf(xv.w, wv.w, acc[e]);
        }
    }
    #pragma unroll
    for (int e = 0; e < NE; e++) {
        #pragma unroll
        for (int o = 16; o > 0; o >>= 1) acc[e] += __shfl_xor_sync(0xffffffffu, acc[e], o);
    }
    if (lane == 0) {
        #pragma unroll
        for (int e = 0; e < NE; e++) part[warp][e] = acc[e];
    }
    __syncthreads();
    if (hf == 0 && lane == 0) {
        float p[NE];
        #pragma unroll
        for (int e = 0; e < NE; e++) p[e] = part[warp][e] + part[warp + 1][e];
        float m = p[0];
        #pragma unroll
        for (int e = 1; e < NE; e++) m = fmaxf(m, p[e]);
        float s = 0.f;
        #pragma unroll
        for (int e = 0; e < NE; e++) { p[e] = __expf(p[e] - m); s += p[e]; }
        float inv = 1.f / s;
        #pragma unroll
        for (int e = 0; e < NE; e++) p[e] *= inv;
        int i1 = 0; float m1 = p[0];
        #pragma unroll
        for (int e = 1; e < NE; e++) if (p[e] > m1) { m1 = p[e]; i1 = e; }
        int i2 = -1; float m2 = -1.f;
        #pragma unroll
        for (int e = 0; e < NE; e++) if (e != i1 && p[e] > m2) { m2 = p[e]; i2 = e; }
        float inv2 = 1.f / (m1 + m2);
        g_sel[t][0] = i1; g_sel[t][1] = i2;
        g_rw[t][0] = m1 * inv2; g_rw[t][1] = m2 * inv2;
        int tm = tmod[t];
        int sel2[2] = { i1, i2 };
        #pragma unroll
        for (int k = 0; k < 2; k++) {
            int e = sel2[k];
            int em = emod[e];
            if (tm != 0 && em != 0) {
                atomicAdd(&g_valid_cnt[e], 1);
                if (tm * em == -1) atomicAdd(&g_mis_cnt[e], 1);
            }
        }
    }
}

// ======================= K2: assign =======================
__global__ void k_assign(const int* __restrict__ emod) {
    int t = blockIdx.x * blockDim.x + threadIdx.x;
    if (t >= BS) return;
    bool skip[NE];
    #pragma unroll
    for (int e = 0; e < NE; e++) {
        int vc = g_valid_cnt[e], mc = g_mis_cnt[e];
        skip[e] = (vc > 0) && (mc == vc) && (emod[e] != 0);
    }
    int s0 = g_sel[t][0], s1 = g_sel[t][1];
    float w0 = g_rw[t][0], w1 = g_rw[t][1];
    if (skip[s0]) w0 = 0.f;
    if (skip[s1]) w1 = 0.f;
    float sum = w0 + w1;
    if (sum > 0.f) { float inv = 1.f / fmaxf(sum, EPSV); w0 *= inv; w1 *= inv; }
    if (w0 > 0.f) {
        int p = atomicAdd(&g_expert_cnt[s0], 1);
        g_expert_tok[s0][p] = t * 2;     g_expert_w[s0][p] = w0;
    }
    if (w1 > 0.f) {
        int p = atomicAdd(&g_expert_cnt[s1], 1);
        g_expert_tok[s1][p] = t * 2 + 1; g_expert_w[s1][p] = w1;
    }
}

// ======================= K5: GEMM1 fp16, B via ldmatrix.trans, 3-stage =======================
// CTA: 128 tokens x 64 f-cols (B tile: 64 k-rows x 128 n-halves [64 g | 64 u], 256B rows)
__global__ void __launch_bounds__(256, 2) k_mma1() {
    int e = blockIdx.z;
    int count = g_expert_cnt[e];
    int m0 = blockIdx.y * 128;
    if (m0 >= count) return;
    int f0 = blockIdx.x * 64;

    extern __shared__ char sm[];
    unsigned sb = smem_u32(sm);
    int tid = threadIdx.x, lane = tid & 31, w = tid >> 5;
    int wm = w & 3, wn = w >> 2;

    int* ts = (int*)sm;
    if (tid < 128) {
        int s = m0 + tid;
        ts[tid] = (s < count) ? (g_expert_tok[e][s] >> 1) : 0;
    }
    __syncthreads();

    const __half* Xb = &g_xr[0][0];
    const __half* Wb = &g_W1[e][0][0];

    // A staging: 128 rows x 8 chunks; B staging: 64 rows x 16 chunks
    unsigned ga_off[4], soffA[4], gbo[4], soffB[4];
    #pragma unroll
    for (int i = 0; i < 4; i++) {
        int idx = tid + i * 256;
        int ra = idx >> 3, ca = idx & 7;
        ga_off[i] = (unsigned)ts[ra] * HD + ca * 8;
        soffA[i] = ra * 128 + ((ca ^ (ra & 7)) << 4);
        int rb = idx >> 4, cb = idx & 15;
        int col = f0 + ((cb & 7) << 3) + ((cb & 8) ? 512 : 0);
        gbo[i] = (unsigned)(rb * TWOF + col);
        soffB[i] = rb * 256 + (((cb ^ ((rb & 7) << 1)) & 15) << 4);
    }

    float acc[2][8][4];
    #pragma unroll
    for (int h = 0; h < 2; h++)
        #pragma unroll
        for (int f = 0; f < 8; f++)
            #pragma unroll
            for (int q = 0; q < 4; q++) acc[h][f][q] = 0.f;

    int l7 = lane & 7;
    int rA0 = (((lane >> 3) & 1) << 3) + l7;
    int cA  = lane >> 4;
    unsigned arow = (unsigned)(wm * 32 + rA0) * 128;
    // B (.trans): lanes 0-7: k0-7 chunk+0; 8-15: k8-15 chunk+0; 16-23: k0-7 chunk+1; 24-31: k8-15 chunk+1
    unsigned brow = (unsigned)rA0 * 256;      // same decomposition: rA0 = k row within 16
    unsigned bswz = (unsigned)(l7 << 1);

    const int NK = HD / 64;
    #pragma unroll
    for (int i = 0; i < 4; i++) {
        CP16(sb + SMH_A(0) + soffA[i], Xb + ga_off[i]);
        CP16(sb + SMH_B(0) + soffB[i], Wb + gbo[i]);
    }
    CPCOMMIT();
    #pragma unroll
    for (int i = 0; i < 4; i++) {
        CP16(sb + SMH_A(1) + soffA[i], Xb + ga_off[i] + 64);
        CP16(sb + SMH_B(1) + soffB[i], Wb + gbo[i] + 64u * TWOF);
    }
    CPCOMMIT();

    for (int kb = 0; kb < NK; kb++) {
        int s = kb % 3;
        if (kb >= NK - 1) { CPWAIT(0); } else { CPWAIT(1); }
        __syncthreads();
        if (kb + 2 < NK) {
            int ns = (kb + 2) % 3;
            #pragma unroll
            for (int i = 0; i < 4; i++) {
                CP16(sb + SMH_A(ns) + soffA[i], Xb + ga_off[i] + (kb + 2) * 64);
                CP16(sb + SMH_B(ns) + soffB[i], Wb + gbo[i] + (unsigned)(kb + 2) * 64u * TWOF);
            }
            CPCOMMIT();
        }
        unsigned sA = sb + SMH_A(s) + arow;
        unsigned sBb = sb + SMH_B(s) + brow;
        #pragma unroll
        for (int kc = 0; kc < 4; kc++) {
            unsigned aoff = (unsigned)(((kc * 2 + cA) ^ l7) << 4);
            unsigned a0, a1, a2, a3, a4, a5, a6, a7;
            LDSM4(a0, a1, a2, a3, sA + aoff);
            LDSM4(a4, a5, a6, a7, sA + 2048 + aoff);
            unsigned sBk = sBb + kc * 4096;
            #pragma unroll
            for (int np = 0; np < 4; np++) {
                int cb = ((np < 2) ? (wn * 4 + np * 2) : (8 + wn * 4 + (np - 2) * 2)) + cA;
                unsigned b0, b1, b2, b3;
                LDSM4T(b0, b1, b2, b3, sBk + (((unsigned)cb ^ bswz) << 4));
                MMAH(acc[0][np * 2],     a0, a1, a2, a3, b0, b1);
                MMAH(acc[0][np * 2 + 1], a0, a1, a2, a3, b2, b3);
                MMAH(acc[1][np * 2],     a4, a5, a6, a7, b0, b1);
                MMAH(acc[1][np * 2 + 1], a4, a5, a6, a7, b2, b3);
            }
        }
    }

    // epilogue: silu(g)*u — frag f (g, f<4) pairs with f+4 (u), same column, same thread
    int p = lane & 3, rlo = lane >> 2;
    #pragma unroll
    for (int h = 0; h < 2; h++) {
        int slot0 = m0 + wm * 32 + h * 16 + rlo;
        int slot1 = slot0 + 8;
        #pragma unroll
        for (int f = 0; f < 4; f++) {
            int j = f0 + wn * 32 + f * 8 + 2 * p;
            if (slot0 < count) {
                float g0 = acc[h][f][0], g1 = acc[h][f][1];
                float u0 = acc[h][f + 4][0], u1 = acc[h][f + 4][1];
                float v0 = g0 / (1.f + __expf(-g0)) * u0;
                float v1 = g1 / (1.f + __expf(-g1)) * u1;
                *(__half2*)&g_act[e][slot0][j] = __floats2half2_rn(v0, v1);
            }
            if (slot1 < count) {
                float g0 = acc[h][f][2], g1 = acc[h][f][3];
                float u0 = acc[h][f + 4][2], u1 = acc[h][f + 4][3];
                float v0 = g0 / (1.f + __expf(-g0)) * u0;
                float v1 = g1 / (1.f + __expf(-g1)) * u1;
                *(__half2*)&g_act[e][slot1][j] = __floats2half2_rn(v0, v1);
            }
        }
    }
}

// ======================= K6: GEMM2 fp16, B via ldmatrix.trans, atomic accumulate =======================
__global__ void __launch_bounds__(256, 2) k_mma2(float* __restrict__ out) {
    int e = blockIdx.z;
    int count = g_expert_cnt[e];
    int m0 = blockIdx.y * 128;
    if (m0 >= count) return;
    int n0 = blockIdx.x * 128;

    extern __shared__ char sm[];
    unsigned sb = smem_u32(sm);
    int tid = threadIdx.x, lane = tid & 31, w = tid >> 5;
    int wm = w & 3, wn = w >> 2;

    int*   tsp = (int*)sm;
    float* tw  = (float*)(sm + 512);
    if (tid < 128) {
        int s = m0 + tid;
        tsp[tid] = (s < count) ? g_expert_tok[e][s] : -1;
        tw[tid]  = (s < count) ? g_expert_w[e][s] : 0.f;
    }
    __syncthreads();

    const __half* Ab = &g_act[e][m0][0];
    const __half* Wb = &g_W2[e][0][0];

    const __half* ga[4]; unsigned soffA[4], gbo[4], soffB[4];
    #pragma unroll
    for (int i = 0; i < 4; i++) {
        int idx = tid + i * 256;
        int ra = idx >> 3, ca = idx & 7;
        ga[i] = Ab + (size_t)ra * FF + ca * 8;
        soffA[i] = ra * 128 + ((ca ^ (ra & 7)) << 4);
        int rb = idx >> 4, cb = idx & 15;
        gbo[i] = (unsigned)(rb * HD + n0 + cb * 8);
        soffB[i] = rb * 256 + (((cb ^ ((rb & 7) << 1)) & 15) << 4);
    }

    float acc[2][8][4];
    #pragma unroll
    for (int h = 0; h < 2; h++)
        #pragma unroll
        for (int f = 0; f < 8; f++)
            #pragma unroll
            for (int q = 0; q < 4; q++) acc[h][f][q] = 0.f;

    int l7 = lane & 7;
    int rA0 = (((lane >> 3) & 1) << 3) + l7;
    int cA  = lane >> 4;
    unsigned arow = (unsigned)(wm * 32 + rA0) * 128;
    unsigned brow = (unsigned)rA0 * 256;
    unsigned bswz = (unsigned)(l7 << 1);

    const int NK = FF / 64;
    #pragma unroll
    for (int i = 0; i < 4; i++) {
        CP16(sb + SMH_A(0) + soffA[i], ga[i]);
        CP16(sb + SMH_B(0) + soffB[i], Wb + gbo[i]);
    }
    CPCOMMIT();
    #pragma unroll
    for (int i = 0; i < 4; i++) {
        CP16(sb + SMH_A(1) + soffA[i], ga[i] + 64);
        CP16(sb + SMH_B(1) + soffB[i], Wb + gbo[i] + 64u * HD);
    }
    CPCOMMIT();

    for (int kb = 0; kb < NK; kb++) {
        int s = kb % 3;
        if (kb >= NK - 1) { CPWAIT(0); } else { CPWAIT(1); }
        __syncthreads();
        if (kb + 2 < NK) {
            int ns = (kb + 2) % 3;
            #pragma unroll
            for (int i = 0; i < 4; i++) {
                CP16(sb + SMH_A(ns) + soffA[i], ga[i] + (kb + 2) * 64);
                CP16(sb + SMH_B(ns) + soffB[i], Wb + gbo[i] + (unsigned)(kb + 2) * 64u * HD);
            }
            CPCOMMIT();
        }
        unsigned sA = sb + SMH_A(s) + arow;
        unsigned sBb = sb + SMH_B(s) + brow;
        #pragma unroll
        for (int kc = 0; kc < 4; kc++) {
            unsigned aoff = (unsigned)(((kc * 2 + cA) ^ l7) << 4);
            unsigned a0, a1, a2, a3, a4, a5, a6, a7;
            LDSM4(a0, a1, a2, a3, sA + aoff);
            LDSM4(a4, a5, a6, a7, sA + 2048 + aoff);
            unsigned sBk = sBb + kc * 4096;
            #pragma unroll
            for (int np = 0; np < 4; np++) {
                int cb = wn * 8 + np * 2 + cA;
                unsigned b0, b1, b2, b3;
                LDSM4T(b0, b1, b2, b3, sBk + (((unsigned)cb ^ bswz) << 4));
                MMAH(acc[0][np * 2],     a0, a1, a2, a3, b0, b1);
                MMAH(acc[0][np * 2 + 1], a0, a1, a2, a3, b2, b3);
                MMAH(acc[1][np * 2],     a4, a5, a6, a7, b0, b1);
                MMAH(acc[1][np * 2 + 1], a4, a5, a6, a7, b2, b3);
            }
        }
    }

    // epilogue: weighted atomic accumulate into out (pre-zeroed; <=2 adds/address)
    int p = lane & 3, rlo = lane >> 2;
    #pragma unroll
    for (int h = 0; h < 2; h++) {
        int r0i = wm * 32 + h * 16 + rlo;
        int r1i = r0i + 8;
        int pk0 = tsp[r0i], pk1 = tsp[r1i];
        float wt0 = tw[r0i], wt1 = tw[r1i];
        #pragma unroll
        for (int f = 0; f < 8; f++) {
            int j = n0 + wn * 64 + f * 8 + 2 * p;
            if (pk0 >= 0) {
                float* dst = out + (size_t)(pk0 >> 1) * HD + j;
                atomicAdd(dst,     acc[h][f][0] * wt0);
                atomicAdd(dst + 1, acc[h][f][1] * wt0);
            }
            if (pk1 >= 0) {
                float* dst = out + (size_t)(pk1 >> 1) * HD + j;
                atomicAdd(dst,     acc[h][f][2] * wt1);
                atomicAdd(dst + 1, acc[h][f][3] * wt1);
            }
        }
    }
}

// ======================= launch =======================
extern "C" void kernel_launch(void* const* d_in, const int* in_sizes, int n_in,
                              void* d_out, int out_size)
{
    const float* x    = (const float*)d_in[0];
    const float* gw   = (const float*)d_in[1];
    const float* gup  = (const float*)d_in[2];
    const float* down = (const float*)d_in[3];
    const int*   tmod = (const int*)d_in[4];
    const int*   emod = (const int*)d_in[5];
    float* out = (float*)d_out;

    cudaFuncSetAttribute(k_mma1, cudaFuncAttributeMaxDynamicSharedMemorySize, SMH_BYTES);
    cudaFuncSetAttribute(k_mma2, cudaFuncAttributeMaxDynamicSharedMemorySize, SMH_BYTES);

    k_prep<<<PREP_BLOCKS, 256>>>(gup, down, (float4*)out);
    k_router<<<512, 256>>>(x, gw, tmod, emod);
    k_assign<<<8, 256>>>(emod);
    k_mma1<<<dim3(8, 16, NE), 256, SMH_BYTES>>>();
    k_mma2<<<dim3(8, 16, NE), 256, SMH_BYTES>>>(out);
}

// round 10
// speedup vs baseline: 1.4397x; 1.4397x over previous
#include <cuda_runtime.h>
#include <cuda_fp16.h>

#define BS   2048
#define HD   1024
#define NE   8
#define FF   512
#define TWOF 1024
#define EPSV 1e-9f

// ======================= device scratch =======================
__device__ int    g_valid_cnt[NE];
__device__ int    g_mis_cnt[NE];
__device__ int    g_expert_cnt[NE];
__device__ int    g_expert_tok[NE][BS];     // packed token*2 + k
__device__ float  g_expert_w[NE][BS];
__device__ int    g_sel[BS][2];
__device__ float  g_rw[BS][2];
__device__ __half g_xr[BS][HD];             // fp16 x (4 MB)
__device__ __half g_W1T[NE][TWOF][HD];      // gate_up^T fp16 (16.8 MB)
__device__ __half g_W2T[NE][HD][FF];        // down^T fp16 (8.4 MB)
__device__ __half g_act[NE][BS][FF];        // silu(g)*u fp16 (16.8 MB)

// ======================= PTX helpers =======================
__device__ __forceinline__ unsigned smem_u32(const void* p) {
    unsigned a;
    asm("{ .reg .u64 t; cvta.to.shared.u64 t, %1; cvt.u32.u64 %0, t; }" : "=r"(a) : "l"(p));
    return a;
}
#define CP16(s, g) asm volatile("cp.async.cg.shared.global [%0], [%1], 16;" :: "r"(s), "l"(g))
#define CPCOMMIT() asm volatile("cp.async.commit_group;" ::: "memory")
#define CPWAIT(n)  asm volatile("cp.async.wait_group %0;" :: "n"(n) : "memory")
#define LDSM4(r0, r1, r2, r3, a) \
    asm volatile("ldmatrix.sync.aligned.m8n8.x4.shared.b16 {%0,%1,%2,%3}, [%4];" \
        : "=r"(r0), "=r"(r1), "=r"(r2), "=r"(r3) : "r"(a))
#define MMAH(c, a0, a1, a2, a3, b0, b1) \
    asm volatile("mma.sync.aligned.m16n8k16.row.col.f32.f16.f16.f32 " \
        "{%0,%1,%2,%3}, {%4,%5,%6,%7}, {%8,%9}, {%0,%1,%2,%3};" \
        : "+f"((c)[0]), "+f"((c)[1]), "+f"((c)[2]), "+f"((c)[3]) \
        : "r"(a0), "r"(a1), "r"(a2), "r"(a3), "r"(b0), "r"(b1))

// dynamic smem: [0,512) tsp ints, [512,1024) tw floats, 3 stages x (A 16KB + B 16KB)
#define SMH_A(s) (1024 + (s) * 32768)
#define SMH_B(s) (1024 + (s) * 32768 + 16384)
#define SMH_BYTES (1024 + 3 * 32768)   // 99328

// ======================= K_prep: transposes -> fp16 + out zero + counters =======================
// grid (32, 48, 8), block (32, 8). by<32: W1 transpose ; by>=32: W2 transpose.
// Output zero-fill distributed grid-stride across all blocks.
#define ZO_F4 (BS * HD / 4)          // 524288 float4
__global__ void __launch_bounds__(256) k_prep(
    const float* __restrict__ gup, const float* __restrict__ down, float4* __restrict__ out)
{
    __shared__ float tile[32][33];
    int e = blockIdx.z;
    int tx = threadIdx.x, ty = threadIdx.y;
    int tid = ty * 32 + tx;
    if (blockIdx.x == 0 && blockIdx.y == 0 && e == 0 && tid < NE) {
        g_valid_cnt[tid] = 0; g_mis_cnt[tid] = 0; g_expert_cnt[tid] = 0;
    }
    // distributed output zeroing
    {
        unsigned bflat = (blockIdx.z * 48u + blockIdx.y) * 32u + blockIdx.x;   // 12288 blocks
        unsigned stride = 12288u * 256u;
        for (unsigned i = bflat * 256u + tid; i < ZO_F4; i += stride)
            out[i] = make_float4(0.f, 0.f, 0.f, 0.f);
    }
    if (blockIdx.y < 32) {
        int kt = blockIdx.x * 32, nt = blockIdx.y * 32;
        const float* src = gup + (size_t)e * HD * TWOF;
        __half* dst = &g_W1T[e][0][0];
        #pragma unroll
        for (int i = 0; i < 32; i += 8)
            tile[ty + i][tx] = src[(size_t)(kt + ty + i) * TWOF + nt + tx];
        __syncthreads();
        #pragma unroll
        for (int i = 0; i < 32; i += 8)
            dst[(size_t)(nt + ty + i) * HD + kt + tx] = __float2half_rn(tile[tx][ty + i]);
    } else {
        int kt = (blockIdx.y - 32) * 32, nt = blockIdx.x * 32;
        const float* src = down + (size_t)e * FF * HD;
        __half* dst = &g_W2T[e][0][0];
        #pragma unroll
        for (int i = 0; i < 32; i += 8)
            tile[ty + i][tx] = src[(size_t)(kt + ty + i) * HD + nt + tx];
        __syncthreads();
        #pragma unroll
        for (int i = 0; i < 32; i += 8)
            dst[(size_t)(nt + ty + i) * FF + kt + tx] = __float2half_rn(tile[tx][ty + i]);
    }
}

// ======================= K1: router, 2 warps/token + x -> fp16 =======================
__global__ void __launch_bounds__(256) k_router(
    const float* __restrict__ x, const float* __restrict__ gw,
    const int* __restrict__ tmod, const int* __restrict__ emod)
{
    __shared__ float sgw[NE * HD];
    __shared__ float part[8][NE];
    for (int i = threadIdx.x; i < NE * HD / 4; i += blockDim.x)
        *(float4*)&sgw[i * 4] = ((const float4*)gw)[i];
    __syncthreads();

    int warp = threadIdx.x >> 5, lane = threadIdx.x & 31;
    int t = blockIdx.x * 4 + (warp >> 1);    // 512 blocks * 4 tokens
    int hf = warp & 1;

    const float4* xr = (const float4*)(x + (size_t)t * HD) + hf * 128;
    __half2* xo = (__half2*)&g_xr[t][0] + hf * 256;
    float acc[NE];
    #pragma unroll
    for (int e = 0; e < NE; e++) acc[e] = 0.f;
    #pragma unroll
    for (int i = 0; i < 4; i++) {
        int q = lane + i * 32;               // 0..127
        float4 xv = xr[q];
        xo[q * 2 + 0] = __floats2half2_rn(xv.x, xv.y);
        xo[q * 2 + 1] = __floats2half2_rn(xv.z, xv.w);
        #pragma unroll
        for (int e = 0; e < NE; e++) {
            const float4 wv = *(const float4*)&sgw[e * HD + (hf * 128 + q) * 4];
            acc[e] = fmaf(xv.x, wv.x, acc[e]);
            acc[e] = fmaf(xv.y, wv.y, acc[e]);
            acc[e] = fmaf(xv.z, wv.z, acc[e]);
            acc[e] = fmaf(xv.w, wv.w, acc[e]);
        }
    }
    #pragma unroll
    for (int e = 0; e < NE; e++) {
        #pragma unroll
        for (int o = 16; o > 0; o >>= 1) acc[e] += __shfl_xor_sync(0xffffffffu, acc[e], o);
    }
    if (lane == 0) {
        #pragma unroll
        for (int e = 0; e < NE; e++) part[warp][e] = acc[e];
    }
    __syncthreads();
    if (hf == 0 && lane == 0) {
        float p[NE];
        #pragma unroll
        for (int e = 0; e < NE; e++) p[e] = part[warp][e] + part[warp + 1][e];
        float m = p[0];
        #pragma unroll
        for (int e = 1; e < NE; e++) m = fmaxf(m, p[e]);
        float s = 0.f;
        #pragma unroll
        for (int e = 0; e < NE; e++) { p[e] = __expf(p[e] - m); s += p[e]; }
        float inv = 1.f / s;
        #pragma unroll
        for (int e = 0; e < NE; e++) p[e] *= inv;
        int i1 = 0; float m1 = p[0];
        #pragma unroll
        for (int e = 1; e < NE; e++) if (p[e] > m1) { m1 = p[e]; i1 = e; }
        int i2 = -1; float m2 = -1.f;
        #pragma unroll
        for (int e = 0; e < NE; e++) if (e != i1 && p[e] > m2) { m2 = p[e]; i2 = e; }
        float inv2 = 1.f / (m1 + m2);
        g_sel[t][0] = i1; g_sel[t][1] = i2;
        g_rw[t][0] = m1 * inv2; g_rw[t][1] = m2 * inv2;
        int tm = tmod[t];
        int sel2[2] = { i1, i2 };
        #pragma unroll
        for (int k = 0; k < 2; k++) {
            int e = sel2[k];
            int em = emod[e];
            if (tm != 0 && em != 0) {
                atomicAdd(&g_valid_cnt[e], 1);
                if (tm * em == -1) atomicAdd(&g_mis_cnt[e], 1);
            }
        }
    }
}

// ======================= K2: assign =======================
__global__ void k_assign(const int* __restrict__ emod) {
    int t = blockIdx.x * blockDim.x + threadIdx.x;
    if (t >= BS) return;
    bool skip[NE];
    #pragma unroll
    for (int e = 0; e < NE; e++) {
        int vc = g_valid_cnt[e], mc = g_mis_cnt[e];
        skip[e] = (vc > 0) && (mc == vc) && (emod[e] != 0);
    }
    int s0 = g_sel[t][0], s1 = g_sel[t][1];
    float w0 = g_rw[t][0], w1 = g_rw[t][1];
    if (skip[s0]) w0 = 0.f;
    if (skip[s1]) w1 = 0.f;
    float sum = w0 + w1;
    if (sum > 0.f) { float inv = 1.f / fmaxf(sum, EPSV); w0 *= inv; w1 *= inv; }
    if (w0 > 0.f) {
        int p = atomicAdd(&g_expert_cnt[s0], 1);
        g_expert_tok[s0][p] = t * 2;     g_expert_w[s0][p] = w0;
    }
    if (w1 > 0.f) {
        int p = atomicAdd(&g_expert_cnt[s1], 1);
        g_expert_tok[s1][p] = t * 2 + 1; g_expert_w[s1][p] = w1;
    }
}

// ======================= K5: GEMM1 fp16 (fused gather) + SiLU*u, 3-stage =======================
__global__ void __launch_bounds__(256, 2) k_mma1() {
    int e = blockIdx.z;
    int count = g_expert_cnt[e];
    int m0 = blockIdx.y * 128;
    if (m0 >= count) return;
    int f0 = blockIdx.x * 64;

    extern __shared__ char sm[];
    unsigned sb = smem_u32(sm);
    int tid = threadIdx.x, lane = tid & 31, w = tid >> 5;
    int wm = w & 3, wn = w >> 2;

    int* ts = (int*)sm;
    if (tid < 128) {
        int s = m0 + tid;
        ts[tid] = (s < count) ? (g_expert_tok[e][s] >> 1) : 0;
    }
    __syncthreads();

    const __half* Xb = &g_xr[0][0];
    const __half* Wb = &g_W1T[e][0][0];

    unsigned ga_off[4]; const __half* gb[4]; unsigned soff[4];
    #pragma unroll
    for (int i = 0; i < 4; i++) {
        int idx = tid + i * 256;
        int r = idx >> 3, c = idx & 7;
        ga_off[i] = (unsigned)ts[r] * HD + c * 8;
        int bh = r >> 6, l = r & 63;
        int col = f0 + bh * 32 + (l & 31);
        int rowg = col + ((l & 32) ? 512 : 0);
        gb[i] = Wb + (size_t)rowg * HD + c * 8;
        soff[i] = r * 128 + ((c ^ (r & 7)) << 4);
    }

    float acc[2][8][4];
    #pragma unroll
    for (int h = 0; h < 2; h++)
        #pragma unroll
        for (int f = 0; f < 8; f++)
            #pragma unroll
            for (int q = 0; q < 4; q++) acc[h][f][q] = 0.f;

    int l7 = lane & 7;
    int rA0 = (((lane >> 3) & 1) << 3) + l7;
    int cA  = lane >> 4;
    int rB0 = ((lane >> 4) << 3) + l7;
    int cB  = (lane >> 3) & 1;
    unsigned arow = (unsigned)(wm * 32 + rA0) * 128;
    unsigned brow0 = (unsigned)(wn * 64 + rB0) * 128;

    const int NK = HD / 64;
    #pragma unroll
    for (int i = 0; i < 4; i++) {
        CP16(sb + SMH_A(0) + soff[i], Xb + ga_off[i]);
        CP16(sb + SMH_B(0) + soff[i], gb[i]);
    }
    CPCOMMIT();
    #pragma unroll
    for (int i = 0; i < 4; i++) {
        CP16(sb + SMH_A(1) + soff[i], Xb + ga_off[i] + 64);
        CP16(sb + SMH_B(1) + soff[i], gb[i] + 64);
    }
    CPCOMMIT();

    for (int kb = 0; kb < NK; kb++) {
        int s = kb % 3;
        if (kb >= NK - 1) { CPWAIT(0); } else { CPWAIT(1); }
        __syncthreads();
        if (kb + 2 < NK) {
            int ns = (kb + 2) % 3;
            #pragma unroll
            for (int i = 0; i < 4; i++) {
                CP16(sb + SMH_A(ns) + soff[i], Xb + ga_off[i] + (kb + 2) * 64);
                CP16(sb + SMH_B(ns) + soff[i], gb[i] + (kb + 2) * 64);
            }
            CPCOMMIT();
        }
        unsigned sA = sb + SMH_A(s) + arow;
        unsigned sB = sb + SMH_B(s) + brow0;
        #pragma unroll
        for (int kc = 0; kc < 4; kc++) {
            unsigned aoff = (unsigned)(((kc * 2 + cA) ^ l7) << 4);
            unsigned boff = (unsigned)(((kc * 2 + cB) ^ l7) << 4);
            unsigned a0, a1, a2, a3, a4, a5, a6, a7;
            LDSM4(a0, a1, a2, a3, sA + aoff);
            LDSM4(a4, a5, a6, a7, sA + 2048 + aoff);
            #pragma unroll
            for (int fg = 0; fg < 4; fg++) {
                unsigned b0, b1, b2, b3;
                LDSM4(b0, b1, b2, b3, sB + fg * 2048 + boff);
                MMAH(acc[0][2 * fg],     a0, a1, a2, a3, b0, b1);
                MMAH(acc[0][2 * fg + 1], a0, a1, a2, a3, b2, b3);
                MMAH(acc[1][2 * fg],     a4, a5, a6, a7, b0, b1);
                MMAH(acc[1][2 * fg + 1], a4, a5, a6, a7, b2, b3);
            }
        }
    }

    // epilogue: silu(g)*u — frag f (g, f<4) pairs with f+4 (u), same column, same thread
    int p = lane & 3, rlo = lane >> 2;
    #pragma unroll
    for (int h = 0; h < 2; h++) {
        int slot0 = m0 + wm * 32 + h * 16 + rlo;
        int slot1 = slot0 + 8;
        #pragma unroll
        for (int f = 0; f < 4; f++) {
            int j = f0 + wn * 32 + f * 8 + 2 * p;
            if (slot0 < count) {
                float g0 = acc[h][f][0], g1 = acc[h][f][1];
                float u0 = acc[h][f + 4][0], u1 = acc[h][f + 4][1];
                float v0 = g0 / (1.f + __expf(-g0)) * u0;
                float v1 = g1 / (1.f + __expf(-g1)) * u1;
                *(__half2*)&g_act[e][slot0][j] = __floats2half2_rn(v0, v1);
            }
            if (slot1 < count) {
                float g0 = acc[h][f][2], g1 = acc[h][f][3];
                float u0 = acc[h][f + 4][2], u1 = acc[h][f + 4][3];
                float v0 = g0 / (1.f + __expf(-g0)) * u0;
                float v1 = g1 / (1.f + __expf(-g1)) * u1;
                *(__half2*)&g_act[e][slot1][j] = __floats2half2_rn(v0, v1);
            }
        }
    }
}

// ======================= K6: GEMM2 fp16, 3-stage, weighted atomic accumulate =======================
__global__ void __launch_bounds__(256, 2) k_mma2(float* __restrict__ out) {
    int e = blockIdx.z;
    int count = g_expert_cnt[e];
    int m0 = blockIdx.y * 128;
    if (m0 >= count) return;
    int n0 = blockIdx.x * 128;

    extern __shared__ char sm[];
    unsigned sb = smem_u32(sm);
    int tid = threadIdx.x, lane = tid & 31, w = tid >> 5;
    int wm = w & 3, wn = w >> 2;

    int*   tsp = (int*)sm;
    float* tw  = (float*)(sm + 512);
    if (tid < 128) {
        int s = m0 + tid;
        tsp[tid] = (s < count) ? g_expert_tok[e][s] : -1;
        tw[tid]  = (s < count) ? g_expert_w[e][s] : 0.f;
    }
    __syncthreads();

    const __half* Ab = &g_act[e][m0][0];
    const __half* Wb = &g_W2T[e][n0][0];

    const __half* ga[4]; const __half* gb[4]; unsigned soff[4];
    #pragma unroll
    for (int i = 0; i < 4; i++) {
        int idx = tid + i * 256;
        int r = idx >> 3, c = idx & 7;
        ga[i] = Ab + (size_t)r * FF + c * 8;
        gb[i] = Wb + (size_t)r * FF + c * 8;
        soff[i] = r * 128 + ((c ^ (r & 7)) << 4);
    }

    float acc[2][8][4];
    #pragma unroll
    for (int h = 0; h < 2; h++)
        #pragma unroll
        for (int f = 0; f < 8; f++)
            #pragma unroll
            for (int q = 0; q < 4; q++) acc[h][f][q] = 0.f;

    int l7 = lane & 7;
    int rA0 = (((lane >> 3) & 1) << 3) + l7;
    int cA  = lane >> 4;
    int rB0 = ((lane >> 4) << 3) + l7;
    int cB  = (lane >> 3) & 1;
    unsigned arow = (unsigned)(wm * 32 + rA0) * 128;
    unsigned brow0 = (unsigned)(wn * 64 + rB0) * 128;

    const int NK = FF / 64;
    #pragma unroll
    for (int i = 0; i < 4; i++) {
        CP16(sb + SMH_A(0) + soff[i], ga[i]);
        CP16(sb + SMH_B(0) + soff[i], gb[i]);
    }
    CPCOMMIT();
    #pragma unroll
    for (int i = 0; i < 4; i++) {
        CP16(sb + SMH_A(1) + soff[i], ga[i] + 64);
        CP16(sb + SMH_B(1) + soff[i], gb[i] + 64);
    }
    CPCOMMIT();

    for (int kb = 0; kb < NK; kb++) {
        int s = kb % 3;
        if (kb >= NK - 1) { CPWAIT(0); } else { CPWAIT(1); }
        __syncthreads();
        if (kb + 2 < NK) {
            int ns = (kb + 2) % 3;
            #pragma unroll
            for (int i = 0; i < 4; i++) {
                CP16(sb + SMH_A(ns) + soff[i], ga[i] + (kb + 2) * 64);
                CP16(sb + SMH_B(ns) + soff[i], gb[i] + (kb + 2) * 64);
            }
            CPCOMMIT();
        }
        unsigned sA = sb + SMH_A(s) + arow;
        unsigned sB = sb + SMH_B(s) + brow0;
        #pragma unroll
        for (int kc = 0; kc < 4; kc++) {
            unsigned aoff = (unsigned)(((kc * 2 + cA) ^ l7) << 4);
            unsigned boff = (unsigned)(((kc * 2 + cB) ^ l7) << 4);
            unsigned a0, a1, a2, a3, a4, a5, a6, a7;
            LDSM4(a0, a1, a2, a3, sA + aoff);
            LDSM4(a4, a5, a6, a7, sA + 2048 + aoff);
            #pragma unroll
            for (int fg = 0; fg < 4; fg++) {
                unsigned b0, b1, b2, b3;
                LDSM4(b0, b1, b2, b3, sB + fg * 2048 + boff);
                MMAH(acc[0][2 * fg],     a0, a1, a2, a3, b0, b1);
                MMAH(acc[0][2 * fg + 1], a0, a1, a2, a3, b2, b3);
                MMAH(acc[1][2 * fg],     a4, a5, a6, a7, b0, b1);
                MMAH(acc[1][2 * fg + 1], a4, a5, a6, a7, b2, b3);
            }
        }
    }

    // epilogue: weighted atomic accumulate into out (pre-zeroed; <=2 adds/address)
    int p = lane & 3, rlo = lane >> 2;
    #pragma unroll
    for (int h = 0; h < 2; h++) {
        int r0i = wm * 32 + h * 16 + rlo;
        int r1i = r0i + 8;
        int pk0 = tsp[r0i], pk1 = tsp[r1i];
        float wt0 = tw[r0i], wt1 = tw[r1i];
        #pragma unroll
        for (int f = 0; f < 8; f++) {
            int j = n0 + wn * 64 + f * 8 + 2 * p;
            if (pk0 >= 0) {
                float* dst = out + (size_t)(pk0 >> 1) * HD + j;
                atomicAdd(dst,     acc[h][f][0] * wt0);
                atomicAdd(dst + 1, acc[h][f][1] * wt0);
            }
            if (pk1 >= 0) {
                float* dst = out + (size_t)(pk1 >> 1) * HD + j;
                atomicAdd(dst,     acc[h][f][2] * wt1);
                atomicAdd(dst + 1, acc[h][f][3] * wt1);
            }
        }
    }
}

// ======================= launch =======================
extern "C" void kernel_launch(void* const* d_in, const int* in_sizes, int n_in,
                              void* d_out, int out_size)
{
    const float* x    = (const float*)d_in[0];
    const float* gw   = (const float*)d_in[1];
    const float* gup  = (const float*)d_in[2];
    const float* down = (const float*)d_in[3];
    const int*   tmod = (const int*)d_in[4];
    const int*   emod = (const int*)d_in[5];
    float* out = (float*)d_out;

    cudaFuncSetAttribute(k_mma1, cudaFuncAttributeMaxDynamicSharedMemorySize, SMH_BYTES);
    cudaFuncSetAttribute(k_mma2, cudaFuncAttributeMaxDynamicSharedMemorySize, SMH_BYTES);

    k_prep<<<dim3(32, 48, NE), dim3(32, 8)>>>(gup, down, (float4*)out);
    k_router<<<512, 256>>>(x, gw, tmod, emod);
    k_assign<<<8, 256>>>(emod);
    k_mma1<<<dim3(8, 16, NE), 256, SMH_BYTES>>>();
    k_mma2<<<dim3(8, 16, NE), 256, SMH_BYTES>>>(out);
}

// round 11
// speedup vs baseline: 1.4784x; 1.0269x over previous
#include <cuda_runtime.h>
#include <cuda_fp16.h>

#define BS   2048
#define HD   1024
#define NE   8
#define FF   512
#define TWOF 1024
#define EPSV 1e-9f

// ======================= device scratch =======================
__device__ int    g_valid_cnt[NE];
__device__ int    g_mis_cnt[NE];
__device__ int    g_expert_cnt[NE];
__device__ int    g_expert_tok[NE][BS];     // packed token*2 + k
__device__ float  g_expert_w[NE][BS];
__device__ int    g_sel[BS][2];
__device__ float  g_rw[BS][2];
__device__ __half g_xr[BS][HD];             // fp16 x (4 MB)
__device__ __half g_W1T[NE][TWOF][HD];      // gate_up^T fp16 (16.8 MB)
__device__ __half g_W2T[NE][HD][FF];        // down^T fp16 (8.4 MB)
__device__ __half g_act[NE][BS][FF];        // silu(g)*u fp16 (16.8 MB)

// ======================= PTX helpers =======================
__device__ __forceinline__ unsigned smem_u32(const void* p) {
    unsigned a;
    asm("{ .reg .u64 t; cvta.to.shared.u64 t, %1; cvt.u32.u64 %0, t; }" : "=r"(a) : "l"(p));
    return a;
}
#define CP16(s, g) asm volatile("cp.async.cg.shared.global [%0], [%1], 16;" :: "r"(s), "l"(g))
#define CPCOMMIT() asm volatile("cp.async.commit_group;" ::: "memory")
#define CPWAIT(n)  asm volatile("cp.async.wait_group %0;" :: "n"(n) : "memory")
#define LDSM4(r0, r1, r2, r3, a) \
    asm volatile("ldmatrix.sync.aligned.m8n8.x4.shared.b16 {%0,%1,%2,%3}, [%4];" \
        : "=r"(r0), "=r"(r1), "=r"(r2), "=r"(r3) : "r"(a))
#define MMAH(c, a0, a1, a2, a3, b0, b1) \
    asm volatile("mma.sync.aligned.m16n8k16.row.col.f32.f16.f16.f32 " \
        "{%0,%1,%2,%3}, {%4,%5,%6,%7}, {%8,%9}, {%0,%1,%2,%3};" \
        : "+f"((c)[0]), "+f"((c)[1]), "+f"((c)[2]), "+f"((c)[3]) \
        : "r"(a0), "r"(a1), "r"(a2), "r"(a3), "r"(b0), "r"(b1))

// dynamic smem: [0,512) tsp ints, [512,1024) tw floats, 3 stages x (A 16KB + B 16KB)
#define SMH_A(s) (1024 + (s) * 32768)
#define SMH_B(s) (1024 + (s) * 32768 + 16384)
#define SMH_BYTES (1024 + 3 * 32768)   // 99328

// ======================= K_prep: coalesced fp32->fp16 transposes + out zero + counters ==========
// 64x64 tiles. Blocks [0,2048): W1 (16 ktiles x 16 ntiles x 8 e). [2048,3072): W2 (8 x 16 x 8).
#define ZO_F4 (BS * HD / 4)          // 524288 float4
#define PREP_BLOCKS 3072
__global__ void __launch_bounds__(256) k_prep(
    const float* __restrict__ gup, const float* __restrict__ down, float4* __restrict__ out)
{
    __shared__ __half tileh[64][72];   // transposed tile [n][k], 144B rows (16B-aligned, padded)
    int b = blockIdx.x;
    int t = threadIdx.x;

    if (b == 0 && t < NE) {
        g_valid_cnt[t] = 0; g_mis_cnt[t] = 0; g_expert_cnt[t] = 0;
    }
    // distributed output zeroing (786432 threads >= 524288 elems)
    {
        unsigned zi = (unsigned)b * 256u + t;
        if (zi < ZO_F4) out[zi] = make_float4(0.f, 0.f, 0.f, 0.f);
    }

    const float* src; __half* dst;
    int kt, nt, src_ld, dst_ld;
    if (b < 2048) {
        int e = b >> 8, rem = b & 255;
        kt = (rem >> 4) * 64; nt = (rem & 15) * 64;
        src = gup + (size_t)e * HD * TWOF;  src_ld = TWOF;
        dst = &g_W1T[e][0][0];              dst_ld = HD;
    } else {
        int b2 = b - 2048;
        int e = b2 >> 7, rem = b2 & 127;
        kt = (rem >> 4) * 64; nt = (rem & 15) * 64;
        src = down + (size_t)e * FF * HD;   src_ld = HD;
        dst = &g_W2T[e][0][0];              dst_ld = FF;
    }

    // load phase: thread (r4 = t>>4, n4 = t&15) loads 4 rows x float4, transposes 4x4 in regs
    int n4 = t & 15, r4 = t >> 4;
    float4 v[4];
    #pragma unroll
    for (int i = 0; i < 4; i++)
        v[i] = *(const float4*)(src + (size_t)(kt + r4 * 4 + i) * src_ld + nt + n4 * 4);
    const float* fv = (const float*)v;
    #pragma unroll
    for (int j = 0; j < 4; j++) {
        __half hh[4];
        #pragma unroll
        for (int i = 0; i < 4; i++) hh[i] = __float2half_rn(fv[i * 4 + j]);
        *(uint2*)&tileh[n4 * 4 + j][r4 * 4] = *(const uint2*)hh;   // 8B column fragment
    }
    __syncthreads();

    // store phase: full 128B-per-row coalesced writes
    #pragma unroll
    for (int j = 0; j < 2; j++) {
        int idx = t + j * 256;
        int rw = idx >> 3, u = idx & 7;
        uint4 val = *(const uint4*)&tileh[rw][u * 8];
        *(uint4*)(dst + (size_t)(nt + rw) * dst_ld + kt + u * 8) = val;
    }
}

// ======================= K1: router, 2 warps/token + x -> fp16 =======================
__global__ void __launch_bounds__(256) k_router(
    const float* __restrict__ x, const float* __restrict__ gw,
    const int* __restrict__ tmod, const int* __restrict__ emod)
{
    __shared__ float sgw[NE * HD];
    __shared__ float part[8][NE];
    for (int i = threadIdx.x; i < NE * HD / 4; i += blockDim.x)
        *(float4*)&sgw[i * 4] = ((const float4*)gw)[i];
    __syncthreads();

    int warp = threadIdx.x >> 5, lane = threadIdx.x & 31;
    int t = blockIdx.x * 4 + (warp >> 1);    // 512 blocks * 4 tokens
    int hf = warp & 1;

    const float4* xr = (const float4*)(x + (size_t)t * HD) + hf * 128;
    __half2* xo = (__half2*)&g_xr[t][0] + hf * 256;
    float acc[NE];
    #pragma unroll
    for (int e = 0; e < NE; e++) acc[e] = 0.f;
    #pragma unroll
    for (int i = 0; i < 4; i++) {
        int q = lane + i * 32;               // 0..127
        float4 xv = xr[q];
        xo[q * 2 + 0] = __floats2half2_rn(xv.x, xv.y);
        xo[q * 2 + 1] = __floats2half2_rn(xv.z, xv.w);
        #pragma unroll
        for (int e = 0; e < NE; e++) {
            const float4 wv = *(const float4*)&sgw[e * HD + (hf * 128 + q) * 4];
            acc[e] = fmaf(xv.x, wv.x, acc[e]);
            acc[e] = fmaf(xv.y, wv.y, acc[e]);
            acc[e] = fmaf(xv.z, wv.z, acc[e]);
            acc[e] = fmaf(xv.w, wv.w, acc[e]);
        }
    }
    #pragma unroll
    for (int e = 0; e < NE; e++) {
        #pragma unroll
        for (int o = 16; o > 0; o >>= 1) acc[e] += __shfl_xor_sync(0xffffffffu, acc[e], o);
    }
    if (lane == 0) {
        #pragma unroll
        for (int e = 0; e < NE; e++) part[warp][e] = acc[e];
    }
    __syncthreads();
    if (hf == 0 && lane == 0) {
        float p[NE];
        #pragma unroll
        for (int e = 0; e < NE; e++) p[e] = part[warp][e] + part[warp + 1][e];
        float m = p[0];
        #pragma unroll
        for (int e = 1; e < NE; e++) m = fmaxf(m, p[e]);
        float s = 0.f;
        #pragma unroll
        for (int e = 0; e < NE; e++) { p[e] = __expf(p[e] - m); s += p[e]; }
        float inv = 1.f / s;
        #pragma unroll
        for (int e = 0; e < NE; e++) p[e] *= inv;
        int i1 = 0; float m1 = p[0];
        #pragma unroll
        for (int e = 1; e < NE; e++) if (p[e] > m1) { m1 = p[e]; i1 = e; }
        int i2 = -1; float m2 = -1.f;
        #pragma unroll
        for (int e = 0; e < NE; e++) if (e != i1 && p[e] > m2) { m2 = p[e]; i2 = e; }
        float inv2 = 1.f / (m1 + m2);
        g_sel[t][0] = i1; g_sel[t][1] = i2;
        g_rw[t][0] = m1 * inv2; g_rw[t][1] = m2 * inv2;
        int tm = tmod[t];
        int sel2[2] = { i1, i2 };
        #pragma unroll
        for (int k = 0; k < 2; k++) {
            int e = sel2[k];
            int em = emod[e];
            if (tm != 0 && em != 0) {
                atomicAdd(&g_valid_cnt[e], 1);
                if (tm * em == -1) atomicAdd(&g_mis_cnt[e], 1);
            }
        }
    }
}

// ======================= K2: assign =======================
__global__ void k_assign(const int* __restrict__ emod) {
    int t = blockIdx.x * blockDim.x + threadIdx.x;
    if (t >= BS) return;
    bool skip[NE];
    #pragma unroll
    for (int e = 0; e < NE; e++) {
        int vc = g_valid_cnt[e], mc = g_mis_cnt[e];
        skip[e] = (vc > 0) && (mc == vc) && (emod[e] != 0);
    }
    int s0 = g_sel[t][0], s1 = g_sel[t][1];
    float w0 = g_rw[t][0], w1 = g_rw[t][1];
    if (skip[s0]) w0 = 0.f;
    if (skip[s1]) w1 = 0.f;
    float sum = w0 + w1;
    if (sum > 0.f) { float inv = 1.f / fmaxf(sum, EPSV); w0 *= inv; w1 *= inv; }
    if (w0 > 0.f) {
        int p = atomicAdd(&g_expert_cnt[s0], 1);
        g_expert_tok[s0][p] = t * 2;     g_expert_w[s0][p] = w0;
    }
    if (w1 > 0.f) {
        int p = atomicAdd(&g_expert_cnt[s1], 1);
        g_expert_tok[s1][p] = t * 2 + 1; g_expert_w[s1][p] = w1;
    }
}

// ======================= K5: GEMM1 fp16 (fused gather) + SiLU*u, 3-stage =======================
__global__ void __launch_bounds__(256, 2) k_mma1() {
    int e = blockIdx.z;
    int count = g_expert_cnt[e];
    int m0 = blockIdx.y * 128;
    if (m0 >= count) return;
    int f0 = blockIdx.x * 64;

    extern __shared__ char sm[];
    unsigned sb = smem_u32(sm);
    int tid = threadIdx.x, lane = tid & 31, w = tid >> 5;
    int wm = w & 3, wn = w >> 2;

    int* ts = (int*)sm;
    if (tid < 128) {
        int s = m0 + tid;
        ts[tid] = (s < count) ? (g_expert_tok[e][s] >> 1) : 0;
    }
    __syncthreads();

    const __half* Xb = &g_xr[0][0];
    const __half* Wb = &g_W1T[e][0][0];

    unsigned ga_off[4]; const __half* gb[4]; unsigned soff[4];
    #pragma unroll
    for (int i = 0; i < 4; i++) {
        int idx = tid + i * 256;
        int r = idx >> 3, c = idx & 7;
        ga_off[i] = (unsigned)ts[r] * HD + c * 8;
        int bh = r >> 6, l = r & 63;
        int col = f0 + bh * 32 + (l & 31);
        int rowg = col + ((l & 32) ? 512 : 0);
        gb[i] = Wb + (size_t)rowg * HD + c * 8;
        soff[i] = r * 128 + ((c ^ (r & 7)) << 4);
    }

    float acc[2][8][4];
    #pragma unroll
    for (int h = 0; h < 2; h++)
        #pragma unroll
        for (int f = 0; f < 8; f++)
            #pragma unroll
            for (int q = 0; q < 4; q++) acc[h][f][q] = 0.f;

    int l7 = lane & 7;
    int rA0 = (((lane >> 3) & 1) << 3) + l7;
    int cA  = lane >> 4;
    int rB0 = ((lane >> 4) << 3) + l7;
    int cB  = (lane >> 3) & 1;
    unsigned arow = (unsigned)(wm * 32 + rA0) * 128;
    unsigned brow0 = (unsigned)(wn * 64 + rB0) * 128;

    const int NK = HD / 64;
    #pragma unroll
    for (int i = 0; i < 4; i++) {
        CP16(sb + SMH_A(0) + soff[i], Xb + ga_off[i]);
        CP16(sb + SMH_B(0) + soff[i], gb[i]);
    }
    CPCOMMIT();
    #pragma unroll
    for (int i = 0; i < 4; i++) {
        CP16(sb + SMH_A(1) + soff[i], Xb + ga_off[i] + 64);
        CP16(sb + SMH_B(1) + soff[i], gb[i] + 64);
    }
    CPCOMMIT();

    for (int kb = 0; kb < NK; kb++) {
        int s = kb % 3;
        if (kb >= NK - 1) { CPWAIT(0); } else { CPWAIT(1); }
        __syncthreads();
        if (kb + 2 < NK) {
            int ns = (kb + 2) % 3;
            #pragma unroll
            for (int i = 0; i < 4; i++) {
                CP16(sb + SMH_A(ns) + soff[i], Xb + ga_off[i] + (kb + 2) * 64);
                CP16(sb + SMH_B(ns) + soff[i], gb[i] + (kb + 2) * 64);
            }
            CPCOMMIT();
        }
        unsigned sA = sb + SMH_A(s) + arow;
        unsigned sB = sb + SMH_B(s) + brow0;
        #pragma unroll
        for (int kc = 0; kc < 4; kc++) {
            unsigned aoff = (unsigned)(((kc * 2 + cA) ^ l7) << 4);
            unsigned boff = (unsigned)(((kc * 2 + cB) ^ l7) << 4);
            unsigned a0, a1, a2, a3, a4, a5, a6, a7;
            LDSM4(a0, a1, a2, a3, sA + aoff);
            LDSM4(a4, a5, a6, a7, sA + 2048 + aoff);
            #pragma unroll
            for (int fg = 0; fg < 4; fg++) {
                unsigned b0, b1, b2, b3;
                LDSM4(b0, b1, b2, b3, sB + fg * 2048 + boff);
                MMAH(acc[0][2 * fg],     a0, a1, a2, a3, b0, b1);
                MMAH(acc[0][2 * fg + 1], a0, a1, a2, a3, b2, b3);
                MMAH(acc[1][2 * fg],     a4, a5, a6, a7, b0, b1);
                MMAH(acc[1][2 * fg + 1], a4, a5, a6, a7, b2, b3);
            }
        }
    }

    // epilogue: silu(g)*u — frag f (g, f<4) pairs with f+4 (u), same column, same thread
    int p = lane & 3, rlo = lane >> 2;
    #pragma unroll
    for (int h = 0; h < 2; h++) {
        int slot0 = m0 + wm * 32 + h * 16 + rlo;
        int slot1 = slot0 + 8;
        #pragma unroll
        for (int f = 0; f < 4; f++) {
            int j = f0 + wn * 32 + f * 8 + 2 * p;
            if (slot0 < count) {
                float g0 = acc[h][f][0], g1 = acc[h][f][1];
                float u0 = acc[h][f + 4][0], u1 = acc[h][f + 4][1];
                float v0 = g0 / (1.f + __expf(-g0)) * u0;
                float v1 = g1 / (1.f + __expf(-g1)) * u1;
                *(__half2*)&g_act[e][slot0][j] = __floats2half2_rn(v0, v1);
            }
            if (slot1 < count) {
                float g0 = acc[h][f][2], g1 = acc[h][f][3];
                float u0 = acc[h][f + 4][2], u1 = acc[h][f + 4][3];
                float v0 = g0 / (1.f + __expf(-g0)) * u0;
                float v1 = g1 / (1.f + __expf(-g1)) * u1;
                *(__half2*)&g_act[e][slot1][j] = __floats2half2_rn(v0, v1);
            }
        }
    }
}

// ======================= K6: GEMM2 fp16, 3-stage, weighted atomic accumulate =======================
__global__ void __launch_bounds__(256, 2) k_mma2(float* __restrict__ out) {
    int e = blockIdx.z;
    int count = g_expert_cnt[e];
    int m0 = blockIdx.y * 128;
    if (m0 >= count) return;
    int n0 = blockIdx.x * 128;

    extern __shared__ char sm[];
    unsigned sb = smem_u32(sm);
    int tid = threadIdx.x, lane = tid & 31, w = tid >> 5;
    int wm = w & 3, wn = w >> 2;

    int*   tsp = (int*)sm;
    float* tw  = (float*)(sm + 512);
    if (tid < 128) {
        int s = m0 + tid;
        tsp[tid] = (s < count) ? g_expert_tok[e][s] : -1;
        tw[tid]  = (s < count) ? g_expert_w[e][s] : 0.f;
    }
    __syncthreads();

    const __half* Ab = &g_act[e][m0][0];
    const __half* Wb = &g_W2T[e][n0][0];

    const __half* ga[4]; const __half* gb[4]; unsigned soff[4];
    #pragma unroll
    for (int i = 0; i < 4; i++) {
        int idx = tid + i * 256;
        int r = idx >> 3, c = idx & 7;
        ga[i] = Ab + (size_t)r * FF + c * 8;
        gb[i] = Wb + (size_t)r * FF + c * 8;
        soff[i] = r * 128 + ((c ^ (r & 7)) << 4);
    }

    float acc[2][8][4];
    #pragma unroll
    for (int h = 0; h < 2; h++)
        #pragma unroll
        for (int f = 0; f < 8; f++)
            #pragma unroll
            for (int q = 0; q < 4; q++) acc[h][f][q] = 0.f;

    int l7 = lane & 7;
    int rA0 = (((lane >> 3) & 1) << 3) + l7;
    int cA  = lane >> 4;
    int rB0 = ((lane >> 4) << 3) + l7;
    int cB  = (lane >> 3) & 1;
    unsigned arow = (unsigned)(wm * 32 + rA0) * 128;
    unsigned brow0 = (unsigned)(wn * 64 + rB0) * 128;

    const int NK = FF / 64;
    #pragma unroll
    for (int i = 0; i < 4; i++) {
        CP16(sb + SMH_A(0) + soff[i], ga[i]);
        CP16(sb + SMH_B(0) + soff[i], gb[i]);
    }
    CPCOMMIT();
    #pragma unroll
    for (int i = 0; i < 4; i++) {
        CP16(sb + SMH_A(1) + soff[i], ga[i] + 64);
        CP16(sb + SMH_B(1) + soff[i], gb[i] + 64);
    }
    CPCOMMIT();

    for (int kb = 0; kb < NK; kb++) {
        int s = kb % 3;
        if (kb >= NK - 1) { CPWAIT(0); } else { CPWAIT(1); }
        __syncthreads();
        if (kb + 2 < NK) {
            int ns = (kb + 2) % 3;
            #pragma unroll
            for (int i = 0; i < 4; i++) {
                CP16(sb + SMH_A(ns) + soff[i], ga[i] + (kb + 2) * 64);
                CP16(sb + SMH_B(ns) + soff[i], gb[i] + (kb + 2) * 64);
            }
            CPCOMMIT();
        }
        unsigned sA = sb + SMH_A(s) + arow;
        unsigned sB = sb + SMH_B(s) + brow0;
        #pragma unroll
        for (int kc = 0; kc < 4; kc++) {
            unsigned aoff = (unsigned)(((kc * 2 + cA) ^ l7) << 4);
            unsigned boff = (unsigned)(((kc * 2 + cB) ^ l7) << 4);
            unsigned a0, a1, a2, a3, a4, a5, a6, a7;
            LDSM4(a0, a1, a2, a3, sA + aoff);
            LDSM4(a4, a5, a6, a7, sA + 2048 + aoff);
            #pragma unroll
            for (int fg = 0; fg < 4; fg++) {
                unsigned b0, b1, b2, b3;
                LDSM4(b0, b1, b2, b3, sB + fg * 2048 + boff);
                MMAH(acc[0][2 * fg],     a0, a1, a2, a3, b0, b1);
                MMAH(acc[0][2 * fg + 1], a0, a1, a2, a3, b2, b3);
                MMAH(acc[1][2 * fg],     a4, a5, a6, a7, b0, b1);
                MMAH(acc[1][2 * fg + 1], a4, a5, a6, a7, b2, b3);
            }
        }
    }

    // epilogue: weighted atomic accumulate into out (pre-zeroed; <=2 adds/address)
    int p = lane & 3, rlo = lane >> 2;
    #pragma unroll
    for (int h = 0; h < 2; h++) {
        int r0i = wm * 32 + h * 16 + rlo;
        int r1i = r0i + 8;
        int pk0 = tsp[r0i], pk1 = tsp[r1i];
        float wt0 = tw[r0i], wt1 = tw[r1i];
        #pragma unroll
        for (int f = 0; f < 8; f++) {
            int j = n0 + wn * 64 + f * 8 + 2 * p;
            if (pk0 >= 0) {
                float* dst = out + (size_t)(pk0 >> 1) * HD + j;
                atomicAdd(dst,     acc[h][f][0] * wt0);
                atomicAdd(dst + 1, acc[h][f][1] * wt0);
            }
            if (pk1 >= 0) {
                float* dst = out + (size_t)(pk1 >> 1) * HD + j;
                atomicAdd(dst,     acc[h][f][2] * wt1);
                atomicAdd(dst + 1, acc[h][f][3] * wt1);
            }
        }
    }
}

// ======================= launch =======================
extern "C" void kernel_launch(void* const* d_in, const int* in_sizes, int n_in,
                              void* d_out, int out_size)
{
    const float* x    = (const float*)d_in[0];
    const float* gw   = (const float*)d_in[1];
    const float* gup  = (const float*)d_in[2];
    const float* down = (const float*)d_in[3];
    const int*   tmod = (const int*)d_in[4];
    const int*   emod = (const int*)d_in[5];
    float* out = (float*)d_out;

    cudaFuncSetAttribute(k_mma1, cudaFuncAttributeMaxDynamicSharedMemorySize, SMH_BYTES);
    cudaFuncSetAttribute(k_mma2, cudaFuncAttributeMaxDynamicSharedMemorySize, SMH_BYTES);

    k_prep<<<PREP_BLOCKS, 256>>>(gup, down, (float4*)out);
    k_router<<<512, 256>>>(x, gw, tmod, emod);
    k_assign<<<8, 256>>>(emod);
    k_mma1<<<dim3(8, 16, NE), 256, SMH_BYTES>>>();
    k_mma2<<<dim3(8, 16, NE), 256, SMH_BYTES>>>(out);
}

// round 12
// speedup vs baseline: 1.4859x; 1.0051x over previous
#include <cuda_runtime.h>
#include <cuda_fp16.h>

#define BS   2048
#define HD   1024
#define NE   8
#define FF   512
#define TWOF 1024
#define EPSV 1e-9f

// ======================= device scratch =======================
__device__ int    g_expert_cnt[NE];
__device__ int    g_expert_tok[NE][BS];     // packed token*2 + k
__device__ float  g_expert_w[NE][BS];
__device__ int    g_sel[BS][2];
__device__ float  g_rw[BS][2];
__device__ int    g_flags[BS];              // bit0: valid0, bit1: mis0, bit2: valid1, bit3: mis1
__device__ __half g_xr[BS][HD];             // fp16 x (4 MB)
__device__ __half g_W1T[NE][TWOF][HD];      // gate_up^T fp16 (16.8 MB)
__device__ __half g_W2T[NE][HD][FF];        // down^T fp16 (8.4 MB)
__device__ __half g_act[NE][BS][FF];        // silu(g)*u fp16 (16.8 MB)

// ======================= PTX helpers =======================
__device__ __forceinline__ unsigned smem_u32(const void* p) {
    unsigned a;
    asm("{ .reg .u64 t; cvta.to.shared.u64 t, %1; cvt.u32.u64 %0, t; }" : "=r"(a) : "l"(p));
    return a;
}
#define CP16(s, g) asm volatile("cp.async.cg.shared.global [%0], [%1], 16;" :: "r"(s), "l"(g))
#define CPCOMMIT() asm volatile("cp.async.commit_group;" ::: "memory")
#define CPWAIT(n)  asm volatile("cp.async.wait_group %0;" :: "n"(n) : "memory")
#define LDSM4(r0, r1, r2, r3, a) \
    asm volatile("ldmatrix.sync.aligned.m8n8.x4.shared.b16 {%0,%1,%2,%3}, [%4];" \
        : "=r"(r0), "=r"(r1), "=r"(r2), "=r"(r3) : "r"(a))
#define MMAH(c, a0, a1, a2, a3, b0, b1) \
    asm volatile("mma.sync.aligned.m16n8k16.row.col.f32.f16.f16.f32 " \
        "{%0,%1,%2,%3}, {%4,%5,%6,%7}, {%8,%9}, {%0,%1,%2,%3};" \
        : "+f"((c)[0]), "+f"((c)[1]), "+f"((c)[2]), "+f"((c)[3]) \
        : "r"(a0), "r"(a1), "r"(a2), "r"(a3), "r"(b0), "r"(b1))

// dynamic smem for MMA kernels
#define SMH_A(s) (1024 + (s) * 32768)
#define SMH_B(s) (1024 + (s) * 32768 + 16384)
#define SMH_BYTES (1024 + 3 * 32768)   // 99328

// ======================= K_fused: prep (transposes + out zero) ∪ router =======================
// Blocks [0,2048): W1 64x64 transpose tiles. [2048,3072): W2 tiles. [3072,3584): router.
#define ZO_F4 (BS * HD / 4)
#define PREP_BLOCKS 3072
#define FUSED_BLOCKS (PREP_BLOCKS + 512)
__global__ void __launch_bounds__(256) k_fused(
    const float* __restrict__ gup, const float* __restrict__ down,
    const float* __restrict__ x, const float* __restrict__ gw,
    const int* __restrict__ tmod, const int* __restrict__ emod,
    float4* __restrict__ out)
{
    __shared__ float smf[NE * HD];   // router: sgw (32KB). prep: uses first 64*72 halves region.
    __shared__ float part[8][NE];
    int b = blockIdx.x;
    int t = threadIdx.x;

    if (b >= PREP_BLOCKS) {
        // ---------------- router role ----------------
        int rb = b - PREP_BLOCKS;
        for (int i = t; i < NE * HD / 4; i += 256)
            *(float4*)&smf[i * 4] = ((const float4*)gw)[i];
        __syncthreads();

        int warp = t >> 5, lane = t & 31;
        int tok = rb * 4 + (warp >> 1);
        int hf = warp & 1;

        const float4* xr = (const float4*)(x + (size_t)tok * HD) + hf * 128;
        __half2* xo = (__half2*)&g_xr[tok][0] + hf * 256;
        float acc[NE];
        #pragma unroll
        for (int e = 0; e < NE; e++) acc[e] = 0.f;
        #pragma unroll
        for (int i = 0; i < 4; i++) {
            int q = lane + i * 32;
            float4 xv = xr[q];
            xo[q * 2 + 0] = __floats2half2_rn(xv.x, xv.y);
            xo[q * 2 + 1] = __floats2half2_rn(xv.z, xv.w);
            #pragma unroll
            for (int e = 0; e < NE; e++) {
                const float4 wv = *(const float4*)&smf[e * HD + (hf * 128 + q) * 4];
                acc[e] = fmaf(xv.x, wv.x, acc[e]);
                acc[e] = fmaf(xv.y, wv.y, acc[e]);
                acc[e] = fmaf(xv.z, wv.z, acc[e]);
                acc[e] = fmaf(xv.w, wv.w, acc[e]);
            }
        }
        #pragma unroll
        for (int e = 0; e < NE; e++) {
            #pragma unroll
            for (int o = 16; o > 0; o >>= 1) acc[e] += __shfl_xor_sync(0xffffffffu, acc[e], o);
        }
        if (lane == 0) {
            #pragma unroll
            for (int e = 0; e < NE; e++) part[warp][e] = acc[e];
        }
        __syncthreads();
        if (hf == 0 && lane == 0) {
            float p[NE];
            #pragma unroll
            for (int e = 0; e < NE; e++) p[e] = part[warp][e] + part[warp + 1][e];
            float m = p[0];
            #pragma unroll
            for (int e = 1; e < NE; e++) m = fmaxf(m, p[e]);
            float s = 0.f;
            #pragma unroll
            for (int e = 0; e < NE; e++) { p[e] = __expf(p[e] - m); s += p[e]; }
            float inv = 1.f / s;
            #pragma unroll
            for (int e = 0; e < NE; e++) p[e] *= inv;
            int i1 = 0; float m1 = p[0];
            #pragma unroll
            for (int e = 1; e < NE; e++) if (p[e] > m1) { m1 = p[e]; i1 = e; }
            int i2 = -1; float m2 = -1.f;
            #pragma unroll
            for (int e = 0; e < NE; e++) if (e != i1 && p[e] > m2) { m2 = p[e]; i2 = e; }
            float inv2 = 1.f / (m1 + m2);
            g_sel[tok][0] = i1; g_sel[tok][1] = i2;
            g_rw[tok][0] = m1 * inv2; g_rw[tok][1] = m2 * inv2;
            int tm = tmod[tok];
            int em0 = emod[i1], em1 = emod[i2];
            int fl = 0;
            if (tm != 0 && em0 != 0) { fl |= 1; if (tm * em0 == -1) fl |= 2; }
            if (tm != 0 && em1 != 0) { fl |= 4; if (tm * em1 == -1) fl |= 8; }
            g_flags[tok] = fl;
        }
        return;
    }

    // ---------------- prep role ----------------
    __half* tileh = (__half*)smf;     // [64][72] transposed tile
    {
        unsigned zi = (unsigned)b * 256u + t;
        if (zi < ZO_F4) out[zi] = make_float4(0.f, 0.f, 0.f, 0.f);
    }
    const float* src; __half* dst;
    int kt, nt, src_ld, dst_ld;
    if (b < 2048) {
        int e = b >> 8, rem = b & 255;
        kt = (rem >> 4) * 64; nt = (rem & 15) * 64;
        src = gup + (size_t)e * HD * TWOF;  src_ld = TWOF;
        dst = &g_W1T[e][0][0];              dst_ld = HD;
    } else {
        int b2 = b - 2048;
        int e = b2 >> 7, rem = b2 & 127;
        kt = (rem >> 4) * 64; nt = (rem & 15) * 64;
        src = down + (size_t)e * FF * HD;   src_ld = HD;
        dst = &g_W2T[e][0][0];              dst_ld = FF;
    }
    int n4 = t & 15, r4 = t >> 4;
    float4 v[4];
    #pragma unroll
    for (int i = 0; i < 4; i++)
        v[i] = *(const float4*)(src + (size_t)(kt + r4 * 4 + i) * src_ld + nt + n4 * 4);
    const float* fv = (const float*)v;
    #pragma unroll
    for (int j = 0; j < 4; j++) {
        __half hh[4];
        #pragma unroll
        for (int i = 0; i < 4; i++) hh[i] = __float2half_rn(fv[i * 4 + j]);
        *(uint2*)&tileh[(n4 * 4 + j) * 72 + r4 * 4] = *(const uint2*)hh;
    }
    __syncthreads();
    #pragma unroll
    for (int j = 0; j < 2; j++) {
        int idx = t + j * 256;
        int rw = idx >> 3, u = idx & 7;
        uint4 val = *(const uint4*)&tileh[rw * 72 + u * 8];
        *(uint4*)(dst + (size_t)(nt + rw) * dst_ld + kt + u * 8) = val;
    }
}

// ======================= K_assign2: single block — counts, skip, renorm, compaction ==========
__global__ void __launch_bounds__(512) k_assign2(const int* __restrict__ emod) {
    __shared__ int vcnt[NE], mcnt[NE], ecnt[NE];
    __shared__ int skip_s[NE];
    int t = threadIdx.x;
    if (t < NE) { vcnt[t] = 0; mcnt[t] = 0; ecnt[t] = 0; }
    __syncthreads();

    int flg[4], sel0[4], sel1[4];
    float w0a[4], w1a[4];
    #pragma unroll
    for (int i = 0; i < 4; i++) {
        int tok = t + i * 512;
        flg[i]  = g_flags[tok];
        sel0[i] = g_sel[tok][0]; sel1[i] = g_sel[tok][1];
        w0a[i]  = g_rw[tok][0];  w1a[i]  = g_rw[tok][1];
        if (flg[i] & 1) { atomicAdd(&vcnt[sel0[i]], 1); if (flg[i] & 2) atomicAdd(&mcnt[sel0[i]], 1); }
        if (flg[i] & 4) { atomicAdd(&vcnt[sel1[i]], 1); if (flg[i] & 8) atomicAdd(&mcnt[sel1[i]], 1); }
    }
    __syncthreads();
    if (t < NE) {
        int vc = vcnt[t], mc = mcnt[t];
        skip_s[t] = (vc > 0) && (mc == vc) && (emod[t] != 0);
    }
    __syncthreads();

    #pragma unroll
    for (int i = 0; i < 4; i++) {
        int tok = t + i * 512;
        float w0 = w0a[i], w1 = w1a[i];
        if (skip_s[sel0[i]]) w0 = 0.f;
        if (skip_s[sel1[i]]) w1 = 0.f;
        float sum = w0 + w1;
        if (sum > 0.f) { float inv = 1.f / fmaxf(sum, EPSV); w0 *= inv; w1 *= inv; }
        if (w0 > 0.f) {
            int p = atomicAdd(&ecnt[sel0[i]], 1);
            g_expert_tok[sel0[i]][p] = tok * 2;     g_expert_w[sel0[i]][p] = w0;
        }
        if (w1 > 0.f) {
            int p = atomicAdd(&ecnt[sel1[i]], 1);
            g_expert_tok[sel1[i]][p] = tok * 2 + 1; g_expert_w[sel1[i]][p] = w1;
        }
    }
    __syncthreads();
    if (t < NE) g_expert_cnt[t] = ecnt[t];
}

// ======================= K_mma1: GEMM1 fp16 (fused gather) + SiLU*u, 3-stage ==============
__global__ void __launch_bounds__(256, 2) k_mma1() {
    int e = blockIdx.z;
    int count = g_expert_cnt[e];
    int m0 = blockIdx.y * 128;
    if (m0 >= count) return;
    int f0 = blockIdx.x * 64;

    extern __shared__ char sm[];
    unsigned sb = smem_u32(sm);
    int tid = threadIdx.x, lane = tid & 31, w = tid >> 5;
    int wm = w & 3, wn = w >> 2;

    int* ts = (int*)sm;
    if (tid < 128) {
        int s = m0 + tid;
        ts[tid] = (s < count) ? (g_expert_tok[e][s] >> 1) : 0;
    }
    __syncthreads();

    const __half* Xb = &g_xr[0][0];
    const __half* Wb = &g_W1T[e][0][0];

    unsigned ga_off[4]; const __half* gb[4]; unsigned soff[4];
    #pragma unroll
    for (int i = 0; i < 4; i++) {
        int idx = tid + i * 256;
        int r = idx >> 3, c = idx & 7;
        ga_off[i] = (unsigned)ts[r] * HD + c * 8;
        int bh = r >> 6, l = r & 63;
        int col = f0 + bh * 32 + (l & 31);
        int rowg = col + ((l & 32) ? 512 : 0);
        gb[i] = Wb + (size_t)rowg * HD + c * 8;
        soff[i] = r * 128 + ((c ^ (r & 7)) << 4);
    }

    float acc[2][8][4];
    #pragma unroll
    for (int h = 0; h < 2; h++)
        #pragma unroll
        for (int f = 0; f < 8; f++)
            #pragma unroll
            for (int q = 0; q < 4; q++) acc[h][f][q] = 0.f;

    int l7 = lane & 7;
    int rA0 = (((lane >> 3) & 1) << 3) + l7;
    int cA  = lane >> 4;
    int rB0 = ((lane >> 4) << 3) + l7;
    int cB  = (lane >> 3) & 1;
    unsigned arow = (unsigned)(wm * 32 + rA0) * 128;
    unsigned brow0 = (unsigned)(wn * 64 + rB0) * 128;

    const int NK = HD / 64;
    #pragma unroll
    for (int i = 0; i < 4; i++) {
        CP16(sb + SMH_A(0) + soff[i], Xb + ga_off[i]);
        CP16(sb + SMH_B(0) + soff[i], gb[i]);
    }
    CPCOMMIT();
    #pragma unroll
    for (int i = 0; i < 4; i++) {
        CP16(sb + SMH_A(1) + soff[i], Xb + ga_off[i] + 64);
        CP16(sb + SMH_B(1) + soff[i], gb[i] + 64);
    }
    CPCOMMIT();

    for (int kb = 0; kb < NK; kb++) {
        int s = kb % 3;
        if (kb >= NK - 1) { CPWAIT(0); } else { CPWAIT(1); }
        __syncthreads();
        if (kb + 2 < NK) {
            int ns = (kb + 2) % 3;
            #pragma unroll
            for (int i = 0; i < 4; i++) {
                CP16(sb + SMH_A(ns) + soff[i], Xb + ga_off[i] + (kb + 2) * 64);
                CP16(sb + SMH_B(ns) + soff[i], gb[i] + (kb + 2) * 64);
            }
            CPCOMMIT();
        }
        unsigned sA = sb + SMH_A(s) + arow;
        unsigned sB = sb + SMH_B(s) + brow0;
        #pragma unroll
        for (int kc = 0; kc < 4; kc++) {
            unsigned aoff = (unsigned)(((kc * 2 + cA) ^ l7) << 4);
            unsigned boff = (unsigned)(((kc * 2 + cB) ^ l7) << 4);
            unsigned a0, a1, a2, a3, a4, a5, a6, a7;
            LDSM4(a0, a1, a2, a3, sA + aoff);
            LDSM4(a4, a5, a6, a7, sA + 2048 + aoff);
            #pragma unroll
            for (int fg = 0; fg < 4; fg++) {
                unsigned b0, b1, b2, b3;
                LDSM4(b0, b1, b2, b3, sB + fg * 2048 + boff);
                MMAH(acc[0][2 * fg],     a0, a1, a2, a3, b0, b1);
                MMAH(acc[0][2 * fg + 1], a0, a1, a2, a3, b2, b3);
                MMAH(acc[1][2 * fg],     a4, a5, a6, a7, b0, b1);
                MMAH(acc[1][2 * fg + 1], a4, a5, a6, a7, b2, b3);
            }
        }
    }

    int p = lane & 3, rlo = lane >> 2;
    #pragma unroll
    for (int h = 0; h < 2; h++) {
        int slot0 = m0 + wm * 32 + h * 16 + rlo;
        int slot1 = slot0 + 8;
        #pragma unroll
        for (int f = 0; f < 4; f++) {
            int j = f0 + wn * 32 + f * 8 + 2 * p;
            if (slot0 < count) {
                float g0 = acc[h][f][0], g1 = acc[h][f][1];
                float u0 = acc[h][f + 4][0], u1 = acc[h][f + 4][1];
                float v0 = g0 / (1.f + __expf(-g0)) * u0;
                float v1 = g1 / (1.f + __expf(-g1)) * u1;
                *(__half2*)&g_act[e][slot0][j] = __floats2half2_rn(v0, v1);
            }
            if (slot1 < count) {
                float g0 = acc[h][f][2], g1 = acc[h][f][3];
                float u0 = acc[h][f + 4][2], u1 = acc[h][f + 4][3];
                float v0 = g0 / (1.f + __expf(-g0)) * u0;
                float v1 = g1 / (1.f + __expf(-g1)) * u1;
                *(__half2*)&g_act[e][slot1][j] = __floats2half2_rn(v0, v1);
            }
        }
    }
}

// ======================= K_mma2: GEMM2 fp16, 3-stage, weighted atomic accumulate ==========
__global__ void __launch_bounds__(256, 2) k_mma2(float* __restrict__ out) {
    int e = blockIdx.z;
    int count = g_expert_cnt[e];
    int m0 = blockIdx.y * 128;
    if (m0 >= count) return;
    int n0 = blockIdx.x * 128;

    extern __shared__ char sm[];
    unsigned sb = smem_u32(sm);
    int tid = threadIdx.x, lane = tid & 31, w = tid >> 5;
    int wm = w & 3, wn = w >> 2;

    int*   tsp = (int*)sm;
    float* tw  = (float*)(sm + 512);
    if (tid < 128) {
        int s = m0 + tid;
        tsp[tid] = (s < count) ? g_expert_tok[e][s] : -1;
        tw[tid]  = (s < count) ? g_expert_w[e][s] : 0.f;
    }
    __syncthreads();

    const __half* Ab = &g_act[e][m0][0];
    const __half* Wb = &g_W2T[e][n0][0];

    const __half* ga[4]; const __half* gb[4]; unsigned soff[4];
    #pragma unroll
    for (int i = 0; i < 4; i++) {
        int idx = tid + i * 256;
        int r = idx >> 3, c = idx & 7;
        ga[i] = Ab + (size_t)r * FF + c * 8;
        gb[i] = Wb + (size_t)r * FF + c * 8;
        soff[i] = r * 128 + ((c ^ (r & 7)) << 4);
    }

    float acc[2][8][4];
    #pragma unroll
    for (int h = 0; h < 2; h++)
        #pragma unroll
        for (int f = 0; f < 8; f++)
            #pragma unroll
            for (int q = 0; q < 4; q++) acc[h][f][q] = 0.f;

    int l7 = lane & 7;
    int rA0 = (((lane >> 3) & 1) << 3) + l7;
    int cA  = lane >> 4;
    int rB0 = ((lane >> 4) << 3) + l7;
    int cB  = (lane >> 3) & 1;
    unsigned arow = (unsigned)(wm * 32 + rA0) * 128;
    unsigned brow0 = (unsigned)(wn * 64 + rB0) * 128;

    const int NK = FF / 64;
    #pragma unroll
    for (int i = 0; i < 4; i++) {
        CP16(sb + SMH_A(0) + soff[i], ga[i]);
        CP16(sb + SMH_B(0) + soff[i], gb[i]);
    }
    CPCOMMIT();
    #pragma unroll
    for (int i = 0; i < 4; i++) {
        CP16(sb + SMH_A(1) + soff[i], ga[i] + 64);
        CP16(sb + SMH_B(1) + soff[i], gb[i] + 64);
    }
    CPCOMMIT();

    for (int kb = 0; kb < NK; kb++) {
        int s = kb % 3;
        if (kb >= NK - 1) { CPWAIT(0); } else { CPWAIT(1); }
        __syncthreads();
        if (kb + 2 < NK) {
            int ns = (kb + 2) % 3;
            #pragma unroll
            for (int i = 0; i < 4; i++) {
                CP16(sb + SMH_A(ns) + soff[i], ga[i] + (kb + 2) * 64);
                CP16(sb + SMH_B(ns) + soff[i], gb[i] + (kb + 2) * 64);
            }
            CPCOMMIT();
        }
        unsigned sA = sb + SMH_A(s) + arow;
        unsigned sB = sb + SMH_B(s) + brow0;
        #pragma unroll
        for (int kc = 0; kc < 4; kc++) {
            unsigned aoff = (unsigned)(((kc * 2 + cA) ^ l7) << 4);
            unsigned boff = (unsigned)(((kc * 2 + cB) ^ l7) << 4);
            unsigned a0, a1, a2, a3, a4, a5, a6, a7;
            LDSM4(a0, a1, a2, a3, sA + aoff);
            LDSM4(a4, a5, a6, a7, sA + 2048 + aoff);
            #pragma unroll
            for (int fg = 0; fg < 4; fg++) {
                unsigned b0, b1, b2, b3;
                LDSM4(b0, b1, b2, b3, sB + fg * 2048 + boff);
                MMAH(acc[0][2 * fg],     a0, a1, a2, a3, b0, b1);
                MMAH(acc[0][2 * fg + 1], a0, a1, a2, a3, b2, b3);
                MMAH(acc[1][2 * fg],     a4, a5, a6, a7, b0, b1);
                MMAH(acc[1][2 * fg + 1], a4, a5, a6, a7, b2, b3);
            }
        }
    }

    int p = lane & 3, rlo = lane >> 2;
    #pragma unroll
    for (int h = 0; h < 2; h++) {
        int r0i = wm * 32 + h * 16 + rlo;
        int r1i = r0i + 8;
        int pk0 = tsp[r0i], pk1 = tsp[r1i];
        float wt0 = tw[r0i], wt1 = tw[r1i];
        #pragma unroll
        for (int f = 0; f < 8; f++) {
            int j = n0 + wn * 64 + f * 8 + 2 * p;
            if (pk0 >= 0) {
                float* dst = out + (size_t)(pk0 >> 1) * HD + j;
                atomicAdd(dst,     acc[h][f][0] * wt0);
                atomicAdd(dst + 1, acc[h][f][1] * wt0);
            }
            if (pk1 >= 0) {
                float* dst = out + (size_t)(pk1 >> 1) * HD + j;
                atomicAdd(dst,     acc[h][f][2] * wt1);
                atomicAdd(dst + 1, acc[h][f][3] * wt1);
            }
        }
    }
}

// ======================= launch =======================
extern "C" void kernel_launch(void* const* d_in, const int* in_sizes, int n_in,
                              void* d_out, int out_size)
{
    const float* x    = (const float*)d_in[0];
    const float* gw   = (const float*)d_in[1];
    const float* gup  = (const float*)d_in[2];
    const float* down = (const float*)d_in[3];
    const int*   tmod = (const int*)d_in[4];
    const int*   emod = (const int*)d_in[5];
    float* out = (float*)d_out;

    cudaFuncSetAttribute(k_mma1, cudaFuncAttributeMaxDynamicSharedMemorySize, SMH_BYTES);
    cudaFuncSetAttribute(k_mma2, cudaFuncAttributeMaxDynamicSharedMemorySize, SMH_BYTES);

    k_fused<<<FUSED_BLOCKS, 256>>>(gup, down, x, gw, tmod, emod, (float4*)out);
    k_assign2<<<1, 512>>>(emod);
    k_mma1<<<dim3(8, 16, NE), 256, SMH_BYTES>>>();
    k_mma2<<<dim3(8, 16, NE), 256, SMH_BYTES>>>(out);
}